// round 11
// baseline (speedup 1.0000x reference)
#include <cuda_runtime.h>
#include <math.h>

#define B_    128
#define TP2   2050
#define T_    2049
#define H_    64
#define G7    448     // 7*H real gates
#define K_    100
#define KE    103     // K+3 rows in in_emb
#define OPT   64      // out-proj threads (warps 0-1)
#define MVT   256     // matvec threads (warps 2-9)
#define NTHR  320     // 10 warps
#define NCTA  64      // 2 batch rows per CTA

// Packed input-projection table: pre2[e][m] = {pre(gate y*64+j), pre(gate (y+4)*64+j)}
__device__ float2 g_pretab2[KE * MVT];

__global__ void build_pretab(const float* __restrict__ in_emb,
                             const float* __restrict__ Wx,
                             const float* __restrict__ bias) {
    int e = blockIdx.x;
    int t = threadIdx.x;            // 0..255
    int j = t >> 2, y = t & 3;
    int glo = y * H_ + j;
    float lo = bias[glo];
#pragma unroll
    for (int k = 0; k < H_; ++k)
        lo = fmaf(in_emb[e * H_ + k], Wx[k * G7 + glo], lo);
    float hi = 0.f;
    if (y < 3) {
        int ghi = (y + 4) * H_ + j;
        hi = bias[ghi];
#pragma unroll
        for (int k = 0; k < H_; ++k)
            hi = fmaf(in_emb[e * H_ + k], Wx[k * G7 + ghi], hi);
    }
    g_pretab2[e * MVT + t] = make_float2(lo, hi);
}

// ---- packed f32x2 helpers ----
typedef unsigned long long u64;
__device__ __forceinline__ u64 pack2(float x, float y) {
    u64 r; asm("mov.b64 %0, {%1, %2};" : "=l"(r) : "f"(x), "f"(y)); return r;
}
__device__ __forceinline__ float2 unpack2(u64 v) {
    float2 r; asm("mov.b64 {%0, %1}, %2;" : "=f"(r.x), "=f"(r.y) : "l"(v)); return r;
}
__device__ __forceinline__ u64 ffma2_(u64 a, u64 b, u64 c) {
    u64 d; asm("fma.rn.f32x2 %0, %1, %2, %3;" : "=l"(d) : "l"(a), "l"(b), "l"(c));
    return d;
}
__device__ __forceinline__ u64 fadd2_(u64 a, u64 b) {
    u64 d; asm("add.rn.f32x2 %0, %1, %2;" : "=l"(d) : "l"(a), "l"(b));
    return d;
}

// ---- MUFU-based activations ----
__device__ __forceinline__ float tanh_ap(float x) {
    float y; asm("tanh.approx.f32 %0, %1;" : "=f"(y) : "f"(x)); return y;
}
__device__ __forceinline__ float ex2_(float x) {
    float y; asm("ex2.approx.f32 %0, %1;" : "=f"(y) : "f"(x)); return y;
}
__device__ __forceinline__ float lg2_(float x) {
    float y; asm("lg2.approx.f32 %0, %1;" : "=f"(y) : "f"(x)); return y;
}
__device__ __forceinline__ float fast_softplus(float x) {      // for outputs
    float e = __expf(-fabsf(x));
    return fmaxf(x, 0.f) + __logf(1.0f + e);
}
#define LOG2E 1.4426950408889634f

__global__ void __launch_bounds__(NTHR, 1)
scan_kernel(const int*   __restrict__ event_t,
            const float* __restrict__ dtime_t,
            const float* __restrict__ Wh,
            const float* __restrict__ out_emb,
            float*       __restrict__ out) {
    extern __shared__ float smem[];
    float2* pretab_s = (float2*)smem;                  // KE*MVT float2 (206 KB)
    // h buffers: row0 buf0 @0, row0 buf1 @64, row1 buf0 @128, row1 buf1 @192
    float*  h_s      = smem + 2 * KE * MVT;

    const int tid  = threadIdx.x;
    const int bb   = blockIdx.x;
    const int lane = tid & 31;

    const int*   ev0_row = event_t + (2 * bb) * TP2;
    const int*   ev1_row = event_t + (2 * bb + 1) * TP2;
    const float* dt0_row = dtime_t + (2 * bb) * TP2;
    const float* dt1_row = dtime_t + (2 * bb + 1) * TP2;
    float* out0_row = out + (size_t)(2 * bb) * T_ * K_;
    float* out1_row = out + (size_t)(2 * bb + 1) * T_ * K_;

    // ---- Stage packed PreTable into shared memory ----
    {
        const float4* src = (const float4*)g_pretab2;
        float4*       dst = (float4*)pretab_s;
        for (int i = tid; i < KE * MVT / 2; i += NTHR) dst[i] = src[i];
    }
    if (tid < H_) { h_s[H_ + tid] = 0.f; h_s[3 * H_ + tid] = 0.f; }  // h_{-1} = 0

    if (tid >= OPT) {
        // ===== matvec/update: warps 2-9, both batch rows, shared weights =====
        const int m = tid - OPT;             // 0..255
        const int y = m & 3;                 // gates y and y+4
        const int j = m >> 2;                // hidden unit 0..63
        const int base = lane & ~3;          // lane of y==0 in this 4-lane group

        // Register-resident Wh columns for gates glo = y*64+j, ghi = (y+4)*64+j
        u64 wlo[H_ / 2], whi[H_ / 2];
        {
            const int glo = y * H_ + j;
#pragma unroll
            for (int k2 = 0; k2 < H_ / 2; ++k2)
                wlo[k2] = pack2(Wh[(2 * k2) * G7 + glo], Wh[(2 * k2 + 1) * G7 + glo]);
            if (y < 3) {
                const int ghi = (y + 4) * H_ + j;
#pragma unroll
                for (int k2 = 0; k2 < H_ / 2; ++k2)
                    whi[k2] = pack2(Wh[(2 * k2) * G7 + ghi], Wh[(2 * k2 + 1) * G7 + ghi]);
            } else {
#pragma unroll
                for (int k2 = 0; k2 < H_ / 2; ++k2) whi[k2] = 0ull;
            }
        }

        float c0 = 0.f, cb0 = 0.f, c1 = 0.f, cb1 = 0.f;   // valid in y==0 lanes
        const float s0 = (y == 2) ? 1.0f : 0.5f;
        const float s1 = (y == 2) ? 1.0f : 0.5f;
        const float s2 = (y == 2) ? 0.0f : 0.5f;

        const float* hr0 = h_s + H_;         // row0 h_{t-1}
        float*       hw0 = h_s;              // row0 h_t
        const float* hr1 = h_s + 3 * H_;     // row1 h_{t-1}
        float*       hw1 = h_s + 2 * H_;     // row1 h_t

        __syncthreads();

        int   ev0  = ev0_row[0], ev1 = ev1_row[0];
        float dtv0 = dt0_row[1], dtv1 = dt1_row[1];
        float2 pre0 = pretab_s[ev0 * MVT + m];
        float2 pre1 = pretab_s[ev1 * MVT + m];

        for (int t = 0; t < T_; ++t) {
            const int   ev0n = ev0_row[t + 1];
            const int   ev1n = ev1_row[t + 1];
            const int   tc   = (t + 2 < TP2) ? (t + 2) : (TP2 - 1);
            const float dt0n = dt0_row[tc];
            const float dt1n = dt1_row[tc];

            // ---- four dot products (2 gates × 2 rows), shared weights ----
            const ulonglong2* h20 = (const ulonglong2*)hr0;
            const ulonglong2* h21 = (const ulonglong2*)hr1;
            u64 aL00 = pack2(pre0.x, 0.f), aL01 = 0ull;
            u64 aH00 = pack2(pre0.y, 0.f), aH01 = 0ull;
            u64 aL10 = pack2(pre1.x, 0.f), aL11 = 0ull;
            u64 aH10 = pack2(pre1.y, 0.f), aH11 = 0ull;
#pragma unroll
            for (int k4 = 0; k4 < 16; ++k4) {
                ulonglong2 hp0 = h20[k4];
                ulonglong2 hp1 = h21[k4];
                aH00 = ffma2_(hp0.x, whi[2 * k4],     aH00);
                aH01 = ffma2_(hp0.y, whi[2 * k4 + 1], aH01);
                aH10 = ffma2_(hp1.x, whi[2 * k4],     aH10);
                aH11 = ffma2_(hp1.y, whi[2 * k4 + 1], aH11);
                aL00 = ffma2_(hp0.x, wlo[2 * k4],     aL00);
                aL01 = ffma2_(hp0.y, wlo[2 * k4 + 1], aL01);
                aL10 = ffma2_(hp1.x, wlo[2 * k4],     aL10);
                aL11 = ffma2_(hp1.y, wlo[2 * k4 + 1], aL11);
            }
            // hi reduces first — delta lanes' MUFU chains gate the last shfl
            float2 rH0 = unpack2(fadd2_(aH00, aH01));
            float2 rH1 = unpack2(fadd2_(aH10, aH11));
            const float gHi0 = rH0.x + rH0.y;
            const float gHi1 = rH1.x + rH1.y;
            float aHi0, aHi1;
            if (y == 2) {
                aHi0 = ex2_(-dtv0 * lg2_(1.0f + ex2_(gHi0 * LOG2E)));
                aHi1 = ex2_(-dtv1 * lg2_(1.0f + ex2_(gHi1 * LOG2E)));
            } else {
                aHi0 = fmaf(0.5f, tanh_ap(0.5f * gHi0), 0.5f);
                aHi1 = fmaf(0.5f, tanh_ap(0.5f * gHi1), 0.5f);
            }

            float2 rL0 = unpack2(fadd2_(aL00, aL01));
            float2 rL1 = unpack2(fadd2_(aL10, aL11));
            const float aLo0 = fmaf(s1, tanh_ap(s0 * (rL0.x + rL0.y)), s2);
            const float aLo1 = fmaf(s1, tanh_ap(s0 * (rL1.x + rL1.y)), s2);

            // prefetch next step's pretab entries (off the critical chain)
            pre0 = pretab_s[ev0n * MVT + m];
            pre1 = pretab_s[ev1n * MVT + m];

            // ---- gather gates within the 4-lane group (both rows) ----
            const float fb0 = __shfl_sync(0xffffffffu, aHi0, base + 1);
            const float ee0 = __shfl_sync(0xffffffffu, aHi0, base + 2);
            const float fb1 = __shfl_sync(0xffffffffu, aHi1, base + 1);
            const float ee1 = __shfl_sync(0xffffffffu, aHi1, base + 2);
            const float fv0 = __shfl_sync(0xffffffffu, aLo0, base + 1);
            const float zv0 = __shfl_sync(0xffffffffu, aLo0, base + 2);
            const float ov0 = __shfl_sync(0xffffffffu, aLo0, base + 3);
            const float fv1 = __shfl_sync(0xffffffffu, aLo1, base + 1);
            const float zv1 = __shfl_sync(0xffffffffu, aLo1, base + 2);
            const float ov1 = __shfl_sync(0xffffffffu, aLo1, base + 3);

            // ---- cell updates (meaningful in y==0 lanes) ----
            const float ci0  = fmaf(fv0, c0, aLo0 * zv0);
            const float cbi0 = fmaf(fb0, cb0, aHi0 * zv0);
            const float cn0  = fmaf(ci0 - cbi0, ee0, cbi0);
            const float ci1  = fmaf(fv1, c1, aLo1 * zv1);
            const float cbi1 = fmaf(fb1, cb1, aHi1 * zv1);
            const float cn1  = fmaf(ci1 - cbi1, ee1, cbi1);
            c0 = cn0; cb0 = cbi0;
            c1 = cn1; cb1 = cbi1;
            const float hn0 = ov0 * tanh_ap(cn0);
            const float hn1 = ov1 * tanh_ap(cn1);
            if (y == 0) { hw0[j] = hn0; hw1[j] = hn1; }

            __syncthreads();
            float* tmp0 = hw0; hw0 = (float*)hr0; hr0 = tmp0;
            float* tmp1 = hw1; hw1 = (float*)hr1; hr1 = tmp1;
            ev0 = ev0n; ev1 = ev1n;
            dtv0 = dt0n; dtv1 = dt1n;
        }
    } else {
        // ===== out-proj: warps 0-1; 2 logits × 2 rows per thread =====
        const int ot = tid;                  // 0..63, active < 50
        const bool on = (ot < 50);
        const int k0 = 2 * ot, k1 = 2 * ot + 1;
        u64 oe0[H_ / 2], oe1[H_ / 2];
        if (on) {
#pragma unroll
            for (int i = 0; i < H_ / 2; ++i) {
                oe0[i] = pack2(out_emb[k0 * H_ + 2 * i], out_emb[k0 * H_ + 2 * i + 1]);
                oe1[i] = pack2(out_emb[k1 * H_ + 2 * i], out_emb[k1 * H_ + 2 * i + 1]);
            }
        } else {
#pragma unroll
            for (int i = 0; i < H_ / 2; ++i) { oe0[i] = 0ull; oe1[i] = 0ull; }
        }

        __syncthreads();

        for (int t = 0; t < T_; ++t) {
            if (t > 0) {
                const int off = ((t - 1) & 1) ? H_ : 0;
                const ulonglong2* hp0 = (const ulonglong2*)(h_s + off);
                const ulonglong2* hp1 = (const ulonglong2*)(h_s + 2 * H_ + off);
                u64 s00 = 0ull, s01 = 0ull;   // logit k0, row0
                u64 s10 = 0ull, s11 = 0ull;   // logit k1, row0
                u64 s20 = 0ull, s21 = 0ull;   // logit k0, row1
                u64 s30 = 0ull, s31 = 0ull;   // logit k1, row1
#pragma unroll
                for (int i = 0; i < 16; ++i) {
                    ulonglong2 hv0 = hp0[i];
                    ulonglong2 hv1 = hp1[i];
                    s00 = ffma2_(hv0.x, oe0[2 * i],     s00);
                    s01 = ffma2_(hv0.y, oe0[2 * i + 1], s01);
                    s10 = ffma2_(hv0.x, oe1[2 * i],     s10);
                    s11 = ffma2_(hv0.y, oe1[2 * i + 1], s11);
                    s20 = ffma2_(hv1.x, oe0[2 * i],     s20);
                    s21 = ffma2_(hv1.y, oe0[2 * i + 1], s21);
                    s30 = ffma2_(hv1.x, oe1[2 * i],     s30);
                    s31 = ffma2_(hv1.y, oe1[2 * i + 1], s31);
                }
                float2 r0 = unpack2(fadd2_(s00, s01));
                float2 r1 = unpack2(fadd2_(s10, s11));
                float2 r2 = unpack2(fadd2_(s20, s21));
                float2 r3 = unpack2(fadd2_(s30, s31));
                if (on) {
                    float* o0 = out0_row + (size_t)(t - 1) * K_;
                    float* o1 = out1_row + (size_t)(t - 1) * K_;
                    o0[k0] = fast_softplus(r0.x + r0.y);
                    o0[k1] = fast_softplus(r1.x + r1.y);
                    o1[k0] = fast_softplus(r2.x + r2.y);
                    o1[k1] = fast_softplus(r3.x + r3.y);
                }
            }
            __syncthreads();
        }

        // ---- drain: final output row from h_{T-1} (buf0, (T-1)&1==0) ----
        {
            const ulonglong2* hp0 = (const ulonglong2*)h_s;
            const ulonglong2* hp1 = (const ulonglong2*)(h_s + 2 * H_);
            u64 s00 = 0ull, s10 = 0ull, s20 = 0ull, s30 = 0ull;
#pragma unroll
            for (int i = 0; i < 16; ++i) {
                ulonglong2 hv0 = hp0[i];
                ulonglong2 hv1 = hp1[i];
                s00 = ffma2_(hv0.x, oe0[2 * i],     s00);
                s00 = ffma2_(hv0.y, oe0[2 * i + 1], s00);
                s10 = ffma2_(hv0.x, oe1[2 * i],     s10);
                s10 = ffma2_(hv0.y, oe1[2 * i + 1], s10);
                s20 = ffma2_(hv1.x, oe0[2 * i],     s20);
                s20 = ffma2_(hv1.y, oe0[2 * i + 1], s20);
                s30 = ffma2_(hv1.x, oe1[2 * i],     s30);
                s30 = ffma2_(hv1.y, oe1[2 * i + 1], s30);
            }
            float2 r0 = unpack2(s00), r1 = unpack2(s10);
            float2 r2 = unpack2(s20), r3 = unpack2(s30);
            if (on) {
                float* o0 = out0_row + (size_t)(T_ - 1) * K_;
                float* o1 = out1_row + (size_t)(T_ - 1) * K_;
                o0[k0] = fast_softplus(r0.x + r0.y);
                o0[k1] = fast_softplus(r1.x + r1.y);
                o1[k0] = fast_softplus(r2.x + r2.y);
                o1[k1] = fast_softplus(r3.x + r3.y);
            }
        }
    }
}

extern "C" void kernel_launch(void* const* d_in, const int* in_sizes, int n_in,
                              void* d_out, int out_size) {
    const int*   ev   = (const int*)  d_in[0];
    const float* dt   = (const float*)d_in[1];
    const float* iemb = (const float*)d_in[2];
    const float* Wx   = (const float*)d_in[3];
    const float* Wh   = (const float*)d_in[4];
    const float* bias = (const float*)d_in[5];
    const float* oemb = (const float*)d_in[6];
    float* out = (float*)d_out;

    const size_t smem_bytes = (size_t)(2 * KE * MVT + 4 * H_ + 16) * sizeof(float);
    cudaFuncSetAttribute(scan_kernel, cudaFuncAttributeMaxDynamicSharedMemorySize,
                         (int)smem_bytes);

    build_pretab<<<KE, MVT>>>(iemb, Wx, bias);
    scan_kernel<<<NCTA, NTHR, smem_bytes>>>(ev, dt, Wh, oemb, out);
}

// round 12
// speedup vs baseline: 1.9164x; 1.9164x over previous
#include <cuda_runtime.h>
#include <math.h>

#define B_    128
#define TP2   2050
#define T_    2049
#define H_    64
#define G7    448     // 7*H real gates
#define K_    100
#define KE    103     // K+3 rows in in_emb
#define OPT   64      // out-proj threads (warps 0-1)
#define MVT   256     // matvec threads (warps 2-9)
#define NTHR  320     // 10 warps

// Packed input-projection table: pre2[e][m] = {pre(gate y*64+j), pre(gate (y+4)*64+j)}
__device__ float2 g_pretab2[KE * MVT];

__global__ void build_pretab(const float* __restrict__ in_emb,
                             const float* __restrict__ Wx,
                             const float* __restrict__ bias) {
    int e = blockIdx.x;
    int t = threadIdx.x;            // 0..255
    int j = t >> 2, y = t & 3;
    int glo = y * H_ + j;
    float lo = bias[glo];
#pragma unroll
    for (int k = 0; k < H_; ++k)
        lo = fmaf(in_emb[e * H_ + k], Wx[k * G7 + glo], lo);
    float hi = 0.f;
    if (y < 3) {
        int ghi = (y + 4) * H_ + j;
        hi = bias[ghi];
#pragma unroll
        for (int k = 0; k < H_; ++k)
            hi = fmaf(in_emb[e * H_ + k], Wx[k * G7 + ghi], hi);
    }
    g_pretab2[e * MVT + t] = make_float2(lo, hi);
}

// ---- packed f32x2 helpers ----
typedef unsigned long long u64;
__device__ __forceinline__ u64 pack2(float x, float y) {
    u64 r; asm("mov.b64 %0, {%1, %2};" : "=l"(r) : "f"(x), "f"(y)); return r;
}
__device__ __forceinline__ float2 unpack2(u64 v) {
    float2 r; asm("mov.b64 {%0, %1}, %2;" : "=f"(r.x), "=f"(r.y) : "l"(v)); return r;
}
__device__ __forceinline__ u64 ffma2_(u64 a, u64 b, u64 c) {
    u64 d; asm("fma.rn.f32x2 %0, %1, %2, %3;" : "=l"(d) : "l"(a), "l"(b), "l"(c));
    return d;
}
__device__ __forceinline__ u64 fadd2_(u64 a, u64 b) {
    u64 d; asm("add.rn.f32x2 %0, %1, %2;" : "=l"(d) : "l"(a), "l"(b));
    return d;
}

// ---- MUFU-based activations ----
__device__ __forceinline__ float tanh_ap(float x) {
    float y; asm("tanh.approx.f32 %0, %1;" : "=f"(y) : "f"(x)); return y;
}
__device__ __forceinline__ float ex2_(float x) {
    float y; asm("ex2.approx.f32 %0, %1;" : "=f"(y) : "f"(x)); return y;
}
__device__ __forceinline__ float lg2_(float x) {
    float y; asm("lg2.approx.f32 %0, %1;" : "=f"(y) : "f"(x)); return y;
}
__device__ __forceinline__ float fast_softplus(float x) {      // for outputs
    float e = __expf(-fabsf(x));
    return fmaxf(x, 0.f) + __logf(1.0f + e);
}
#define LOG2E 1.4426950408889634f

__global__ void __launch_bounds__(NTHR, 1)
scan_kernel(const int*   __restrict__ event_t,
            const float* __restrict__ dtime_t,
            const float* __restrict__ Wh,
            const float* __restrict__ out_emb,
            float*       __restrict__ out) {
    extern __shared__ float smem[];
    float2* pretab_s = (float2*)smem;                  // KE*MVT float2 (206 KB)
    float*  h_s      = smem + 2 * KE * MVT;            // 4*H floats (quad buffered)

    const int tid  = threadIdx.x;
    const int bb   = blockIdx.x;
    const int lane = tid & 31;

    const int*   ev_row  = event_t + bb * TP2;
    const float* dt_row  = dtime_t + bb * TP2;
    float*       out_row = out + (size_t)bb * T_ * K_;

    // ---- Stage packed PreTable into shared memory ----
    {
        const float4* src = (const float4*)g_pretab2;
        float4*       dst = (float4*)pretab_s;
        for (int i = tid; i < KE * MVT / 2; i += NTHR) dst[i] = src[i];
    }
    if (tid < H_) h_s[3 * H_ + tid] = 0.f;   // h_{-1} lives in buf3

    if (tid >= OPT) {
        // ===== matvec/update: warps 2-9 =====
        const int m = tid - OPT;             // 0..255
        const int y = m & 3;                 // gates y and y+4
        const int j = m >> 2;                // hidden unit 0..63
        const int base = lane & ~3;          // lane of y==0 in this 4-lane group

        // Register-resident Wh columns for gates glo = y*64+j, ghi = (y+4)*64+j
        u64 wlo[H_ / 2], whi[H_ / 2];
        {
            const int glo = y * H_ + j;
#pragma unroll
            for (int k2 = 0; k2 < H_ / 2; ++k2)
                wlo[k2] = pack2(Wh[(2 * k2) * G7 + glo], Wh[(2 * k2 + 1) * G7 + glo]);
            if (y < 3) {
                const int ghi = (y + 4) * H_ + j;
#pragma unroll
                for (int k2 = 0; k2 < H_ / 2; ++k2)
                    whi[k2] = pack2(Wh[(2 * k2) * G7 + ghi], Wh[(2 * k2 + 1) * G7 + ghi]);
            } else {
#pragma unroll
                for (int k2 = 0; k2 < H_ / 2; ++k2) whi[k2] = 0ull;
            }
        }

        float c = 0.f, cbv = 0.f;            // valid in y==0 lanes
        const float s0 = (y == 2) ? 1.0f : 0.5f;
        const float s1 = (y == 2) ? 1.0f : 0.5f;
        const float s2 = (y == 2) ? 0.0f : 0.5f;

        __syncthreads();                     // pretab + h_{-1} staged

        int   ev  = ev_row[0];
        float dtv = dt_row[1];
        float2 pre = pretab_s[ev * MVT + m]; // prefetched for t=0

        for (int t = 0; t < T_; ++t) {
            const float* hr = h_s + (((t + 3) & 3) * H_);   // h_{t-1}
            float*       hw = h_s + ((t & 3) * H_);         // h_t

            const int   ev_next = ev_row[t + 1];            // always in-bounds
            const float dt_next = dt_row[(t + 2 < TP2) ? (t + 2) : (TP2 - 1)];

            // ---- two dot products sharing one h read (8 chains, depth 8) ----
            const ulonglong2* h2 = (const ulonglong2*)hr;
            u64 aL0 = pack2(pre.x, 0.f), aL1 = 0ull, aL2 = 0ull, aL3 = 0ull;
            u64 aH0 = pack2(pre.y, 0.f), aH1 = 0ull, aH2 = 0ull, aH3 = 0ull;
#pragma unroll
            for (int k4 = 0; k4 < 16; k4 += 2) {
                ulonglong2 hp = h2[k4];
                aH0 = ffma2_(hp.x, whi[2 * k4],     aH0);
                aH1 = ffma2_(hp.y, whi[2 * k4 + 1], aH1);
                aL0 = ffma2_(hp.x, wlo[2 * k4],     aL0);
                aL1 = ffma2_(hp.y, wlo[2 * k4 + 1], aL1);
                ulonglong2 hq = h2[k4 + 1];
                aH2 = ffma2_(hq.x, whi[2 * k4 + 2], aH2);
                aH3 = ffma2_(hq.y, whi[2 * k4 + 3], aH3);
                aL2 = ffma2_(hq.x, wlo[2 * k4 + 2], aL2);
                aL3 = ffma2_(hq.y, wlo[2 * k4 + 3], aL3);
            }
            // hi reduce first — the delta lane's MUFU chain gates the final shfl
            float2 rH = unpack2(fadd2_(fadd2_(aH0, aH1), fadd2_(aH2, aH3)));
            const float gHi = rH.x + rH.y;
            float aHi;
            if (y == 2) {
                aHi = ex2_(-dtv * lg2_(1.0f + ex2_(gHi * LOG2E)));  // exp(-dt*softplus)
            } else {
                aHi = fmaf(0.5f, tanh_ap(0.5f * gHi), 0.5f);
            }

            float2 rL = unpack2(fadd2_(fadd2_(aL0, aL1), fadd2_(aL2, aL3)));
            const float gLo = rL.x + rL.y;
            const float aLo = fmaf(s1, tanh_ap(s0 * gLo), s2);

            // prefetch next step's pretab entry (off the critical chain)
            pre = pretab_s[ev_next * MVT + m];

            // ---- gather 7 gates of unit j within the 4-lane group ----
            const float fbv = __shfl_sync(0xffffffffu, aHi, base + 1);
            const float ev_ = __shfl_sync(0xffffffffu, aHi, base + 2);
            const float fv  = __shfl_sync(0xffffffffu, aLo, base + 1);
            const float zv  = __shfl_sync(0xffffffffu, aLo, base + 2);
            const float ov  = __shfl_sync(0xffffffffu, aLo, base + 3);

            // ---- cell update (meaningful in y==0 lanes) ----
            const float ci  = fmaf(fv, c, aLo * zv);
            const float cbi = fmaf(fbv, cbv, aHi * zv);
            const float cn  = fmaf(ci - cbi, ev_, cbi);
            c   = cn;
            cbv = cbi;
            const float hn = ov * tanh_ap(cn);
            if (y == 0) hw[j] = hn;

            // barrier only after odd steps (phase = 2 steps); MV step t+1 reads
            // buf t&3 which MV itself just wrote — visible via smem w/o barrier
            // within the warp? NO — cross-warp h needs ordering: use a cheap
            // MV-only guarantee: all MV warps must see h_t before step t+1.
            if (t & 1) {
                __syncthreads();             // full phase barrier (with OP)
            } else {
                asm volatile("bar.sync 1, %0;" :: "r"(MVT) : "memory");  // MV-only
            }
            ev  = ev_next;
            dtv = dt_next;
        }
        __syncthreads();                     // final: publish h_{T-1}
    } else {
        // ===== out-proj: warps 0-1, two h vectors per phase =====
        const int ot = tid;                  // 0..63, active < 50
        const bool on = (ot < 50);
        const int k0 = 2 * ot, k1 = 2 * ot + 1;
        u64 oe0[H_ / 2], oe1[H_ / 2];
        if (on) {
#pragma unroll
            for (int i = 0; i < H_ / 2; ++i) {
                oe0[i] = pack2(out_emb[k0 * H_ + 2 * i], out_emb[k0 * H_ + 2 * i + 1]);
                oe1[i] = pack2(out_emb[k1 * H_ + 2 * i], out_emb[k1 * H_ + 2 * i + 1]);
            }
        } else {
#pragma unroll
            for (int i = 0; i < H_ / 2; ++i) { oe0[i] = 0ull; oe1[i] = 0ull; }
        }

        __syncthreads();                     // pretab + h_{-1} staged

        // phases: after sync p (p=0..1023), h_{2p} and h_{2p+1} are ready
        for (int p = 0; p < (T_ - 1) / 2; ++p) {
            __syncthreads();                 // end of MV phase p
#pragma unroll
            for (int q = 0; q < 2; ++q) {
                const int u = 2 * p + q;
                const float* hb = h_s + ((u & 3) * H_);
                const ulonglong2* hp2 = (const ulonglong2*)hb;
                u64 s00 = 0ull, s01 = 0ull, s10 = 0ull, s11 = 0ull;
#pragma unroll
                for (int i = 0; i < 16; ++i) {
                    ulonglong2 hv = hp2[i];
                    s00 = ffma2_(hv.x, oe0[2 * i],     s00);
                    s01 = ffma2_(hv.y, oe0[2 * i + 1], s01);
                    s10 = ffma2_(hv.x, oe1[2 * i],     s10);
                    s11 = ffma2_(hv.y, oe1[2 * i + 1], s11);
                }
                float2 r0 = unpack2(fadd2_(s00, s01));
                float2 r1 = unpack2(fadd2_(s10, s11));
                if (on) {
                    float* orow = out_row + (size_t)u * K_;
                    orow[k0] = fast_softplus(r0.x + r0.y);
                    orow[k1] = fast_softplus(r1.x + r1.y);
                }
            }
        }
        __syncthreads();                     // final MV step done
        // drain: u = T_-1 = 2048, buf 0
        {
            const ulonglong2* hp2 = (const ulonglong2*)(h_s + ((2048 & 3) * H_));
            u64 s00 = 0ull, s01 = 0ull, s10 = 0ull, s11 = 0ull;
#pragma unroll
            for (int i = 0; i < 16; ++i) {
                ulonglong2 hv = hp2[i];
                s00 = ffma2_(hv.x, oe0[2 * i],     s00);
                s01 = ffma2_(hv.y, oe0[2 * i + 1], s01);
                s10 = ffma2_(hv.x, oe1[2 * i],     s10);
                s11 = ffma2_(hv.y, oe1[2 * i + 1], s11);
            }
            float2 r0 = unpack2(fadd2_(s00, s01));
            float2 r1 = unpack2(fadd2_(s10, s11));
            if (on) {
                float* orow = out_row + (size_t)(T_ - 1) * K_;
                orow[k0] = fast_softplus(r0.x + r0.y);
                orow[k1] = fast_softplus(r1.x + r1.y);
            }
        }
    }
}

extern "C" void kernel_launch(void* const* d_in, const int* in_sizes, int n_in,
                              void* d_out, int out_size) {
    const int*   ev   = (const int*)  d_in[0];
    const float* dt   = (const float*)d_in[1];
    const float* iemb = (const float*)d_in[2];
    const float* Wx   = (const float*)d_in[3];
    const float* Wh   = (const float*)d_in[4];
    const float* bias = (const float*)d_in[5];
    const float* oemb = (const float*)d_in[6];
    float* out = (float*)d_out;

    const size_t smem_bytes = (size_t)(2 * KE * MVT + 4 * H_ + 16) * sizeof(float);
    cudaFuncSetAttribute(scan_kernel, cudaFuncAttributeMaxDynamicSharedMemorySize,
                         (int)smem_bytes);

    build_pretab<<<KE, MVT>>>(iemb, Wx, bias);
    scan_kernel<<<B_, NTHR, smem_bytes>>>(ev, dt, Wh, oemb, out);
}